// round 1
// baseline (speedup 1.0000x reference)
#include <cuda_runtime.h>

// Problem constants (fixed by the dataset)
static constexpr int B_DIM = 8192;   // batch
static constexpr int N_DIM = 2048;   // nodes / features

// Scratch (device globals: allocation-free rule)
__device__ float g_xT[(size_t)N_DIM * B_DIM];   // x transposed:     (N, B)
__device__ float g_lT[(size_t)N_DIM * B_DIM];   // label transposed: (N, B)
__device__ float g_y2[(size_t)B_DIM * N_DIM];   // GEMM A operand = relu(M + cb), flat (B, N)

// ---------------------------------------------------------------------------
// Kernel 1: transpose x (B,N) -> xT (N,B) and label -> lT. z selects tensor.
// ---------------------------------------------------------------------------
__global__ __launch_bounds__(256) void transpose_kernel(
    const float* __restrict__ x, const float* __restrict__ label)
{
    __shared__ float tile[32][33];
    const float* src = blockIdx.z ? label : x;
    float* dst       = blockIdx.z ? g_lT  : g_xT;

    int c = blockIdx.x * 32 + threadIdx.x;   // column in src (node)
    int r = blockIdx.y * 32 + threadIdx.y;   // row in src (batch)
#pragma unroll
    for (int j = 0; j < 32; j += 8)
        tile[threadIdx.y + j][threadIdx.x] = src[(size_t)(r + j) * N_DIM + c];
    __syncthreads();

    int c2 = blockIdx.y * 32 + threadIdx.x;  // column in dst (batch)
    int r2 = blockIdx.x * 32 + threadIdx.y;  // row in dst (node)
#pragma unroll
    for (int j = 0; j < 32; j += 8)
        dst[(size_t)(r2 + j) * B_DIM + c2] = tile[threadIdx.x][threadIdx.y + j];
}

// ---------------------------------------------------------------------------
// Kernel 2: y2 flat(q*8192 + R) = relu( sum_j w0[j]*xT[adj[q][j]][R]
//                                      + sum_j w1[j]*lT[adj[q][j]][R] + cb )
// grid = (8192/(256*4)=8, 2048), 256 threads, float4 per thread.
// ---------------------------------------------------------------------------
__global__ __launch_bounds__(256) void build_y2_kernel(
    const int* __restrict__ adj,
    const float* __restrict__ conv_w,   // (1,2,1,4): w0 = [0..3], w1 = [4..7]
    const float* __restrict__ conv_b)
{
    const int q = blockIdx.y;
    const int r = blockIdx.x * 1024 + threadIdx.x * 4;

    float w[8];
#pragma unroll
    for (int j = 0; j < 8; j++) w[j] = __ldg(&conv_w[j]);
    const float cb = __ldg(&conv_b[0]);

    const int c0 = __ldg(&adj[q * 4 + 0]);
    const int c1 = __ldg(&adj[q * 4 + 1]);
    const int c2 = __ldg(&adj[q * 4 + 2]);
    const int c3 = __ldg(&adj[q * 4 + 3]);

    float4 acc = make_float4(cb, cb, cb, cb);
#define ACC4(buf, col, wj)                                                    \
    {                                                                         \
        float4 v = *(const float4*)&buf[(size_t)(col) * B_DIM + r];           \
        acc.x = fmaf((wj), v.x, acc.x);                                       \
        acc.y = fmaf((wj), v.y, acc.y);                                       \
        acc.z = fmaf((wj), v.z, acc.z);                                       \
        acc.w = fmaf((wj), v.w, acc.w);                                       \
    }
    ACC4(g_xT, c0, w[0]); ACC4(g_xT, c1, w[1]);
    ACC4(g_xT, c2, w[2]); ACC4(g_xT, c3, w[3]);
    ACC4(g_lT, c0, w[4]); ACC4(g_lT, c1, w[5]);
    ACC4(g_lT, c2, w[6]); ACC4(g_lT, c3, w[7]);
#undef ACC4

    acc.x = fmaxf(acc.x, 0.0f);
    acc.y = fmaxf(acc.y, 0.0f);
    acc.z = fmaxf(acc.z, 0.0f);
    acc.w = fmaxf(acc.w, 0.0f);
    *(float4*)&g_y2[(size_t)q * B_DIM + r] = acc;
}

// ---------------------------------------------------------------------------
// Kernel 3: C[m][n] = sum_k g_y2[m][k] * W[n][k] + bias[n]
// M=8192, N=2048, K=2048. 128x128x8 tiling, 256 threads, 8x8 per thread.
// ---------------------------------------------------------------------------
#define GBM 128
#define GBN 128
#define GBK 8

__global__ __launch_bounds__(256) void gemm_kernel(
    const float* __restrict__ W,      // lin_w (N,N), K-major
    const float* __restrict__ bias,   // lin_b (N,)
    float* __restrict__ C)            // out (B,N)
{
    __shared__ float As[GBK][GBM];
    __shared__ float Bs[GBK][GBN];

    const int tid = threadIdx.x;
    const int m0 = blockIdx.y * GBM;
    const int n0 = blockIdx.x * GBN;

    const int lr = tid >> 1;           // 0..127 : tile row for loads
    const int lc = (tid & 1) * 4;      // 0 or 4 : k-offset for float4 load

    const float* Aptr = g_y2 + (size_t)(m0 + lr) * N_DIM + lc;
    const float* Bptr = W    + (size_t)(n0 + lr) * N_DIM + lc;

    const int tr = (tid >> 4) * 8;     // 0,8,...,120
    const int tc = (tid & 15) * 8;     // 0,8,...,120

    float acc[8][8] = {};

    for (int k0 = 0; k0 < N_DIM; k0 += GBK) {
        float4 av = *(const float4*)(Aptr + k0);
        float4 bv = *(const float4*)(Bptr + k0);
        As[lc + 0][lr] = av.x; As[lc + 1][lr] = av.y;
        As[lc + 2][lr] = av.z; As[lc + 3][lr] = av.w;
        Bs[lc + 0][lr] = bv.x; Bs[lc + 1][lr] = bv.y;
        Bs[lc + 2][lr] = bv.z; Bs[lc + 3][lr] = bv.w;
        __syncthreads();

#pragma unroll
        for (int k = 0; k < GBK; k++) {
            float4 a0 = *(const float4*)&As[k][tr];
            float4 a1 = *(const float4*)&As[k][tr + 4];
            float4 b0 = *(const float4*)&Bs[k][tc];
            float4 b1 = *(const float4*)&Bs[k][tc + 4];
            float ra[8] = {a0.x, a0.y, a0.z, a0.w, a1.x, a1.y, a1.z, a1.w};
            float rb[8] = {b0.x, b0.y, b0.z, b0.w, b1.x, b1.y, b1.z, b1.w};
#pragma unroll
            for (int i = 0; i < 8; i++)
#pragma unroll
                for (int j = 0; j < 8; j++)
                    acc[i][j] = fmaf(ra[i], rb[j], acc[i][j]);
        }
        __syncthreads();
    }

    float bb[8];
#pragma unroll
    for (int j = 0; j < 8; j++) bb[j] = __ldg(&bias[n0 + tc + j]);

#pragma unroll
    for (int i = 0; i < 8; i++) {
        float4 v0, v1;
        v0.x = acc[i][0] + bb[0]; v0.y = acc[i][1] + bb[1];
        v0.z = acc[i][2] + bb[2]; v0.w = acc[i][3] + bb[3];
        v1.x = acc[i][4] + bb[4]; v1.y = acc[i][5] + bb[5];
        v1.z = acc[i][6] + bb[6]; v1.w = acc[i][7] + bb[7];
        float* cp = &C[(size_t)(m0 + tr + i) * N_DIM + n0 + tc];
        *(float4*)(cp)     = v0;
        *(float4*)(cp + 4) = v1;
    }
}

// ---------------------------------------------------------------------------
extern "C" void kernel_launch(void* const* d_in, const int* in_sizes, int n_in,
                              void* d_out, int out_size)
{
    const float* x      = (const float*)d_in[0];
    const float* label  = (const float*)d_in[1];
    const int*   adj    = (const int*)  d_in[2];
    const float* conv_w = (const float*)d_in[3];
    const float* conv_b = (const float*)d_in[4];
    const float* lin_w  = (const float*)d_in[5];
    const float* lin_b  = (const float*)d_in[6];
    float* out = (float*)d_out;

    // 1) transpose x, label -> g_xT, g_lT
    {
        dim3 grid(N_DIM / 32, B_DIM / 32, 2);
        dim3 block(32, 8, 1);
        transpose_kernel<<<grid, block>>>(x, label);
    }
    // 2) build y2 = relu(M + cb) in flat (B, N) layout
    {
        dim3 grid(B_DIM / (256 * 4), N_DIM, 1);
        build_y2_kernel<<<grid, 256>>>(adj, conv_w, conv_b);
    }
    // 3) GEMM: out = y2 @ lin_w^T + lin_b
    {
        dim3 grid(N_DIM / GBN, B_DIM / GBM, 1);
        gemm_kernel<<<grid, 256>>>(lin_w, lin_b, out);
    }
}

// round 3
// speedup vs baseline: 2.6824x; 2.6824x over previous
#include <cuda_runtime.h>
#include <cuda_bf16.h>
#include <cstdint>

static constexpr int B_DIM = 8192;   // batch (GEMM M)
static constexpr int N_DIM = 2048;   // nodes / features (GEMM N and K)

// ---------------- scratch (device globals; allocation-free rule) ------------
__device__ float g_xT[(size_t)N_DIM * B_DIM];            // x^T  (N, B)
__device__ float g_lT[(size_t)N_DIM * B_DIM];            // label^T (N, B)
__device__ __nv_bfloat16 g_Ah[(size_t)B_DIM * N_DIM];    // A hi (8192 x 2048)
__device__ __nv_bfloat16 g_Al[(size_t)B_DIM * N_DIM];    // A lo
__device__ __nv_bfloat16 g_Wh[(size_t)N_DIM * N_DIM];    // W hi (2048 x 2048)
__device__ __nv_bfloat16 g_Wl[(size_t)N_DIM * N_DIM];    // W lo

#define SW128(x) ((x) ^ (((x) >> 3) & 0x70))

// ---------------------------- PTX helpers (sm_80+ only) ---------------------
__device__ __forceinline__ uint32_t smem_u32(const void* p) {
    uint32_t a;
    asm("{ .reg .u64 t; cvta.to.shared.u64 t, %1; cvt.u32.u64 %0, t; }"
        : "=r"(a) : "l"(p));
    return a;
}

__device__ __forceinline__ void cp16(uint32_t saddr, const void* gaddr) {
    asm volatile("cp.async.cg.shared.global [%0], [%1], 16;"
                 :: "r"(saddr), "l"(gaddr) : "memory");
}
#define CP_COMMIT() asm volatile("cp.async.commit_group;" ::: "memory")
#define CP_WAIT(n)  asm volatile("cp.async.wait_group %0;" :: "n"(n) : "memory")

__device__ __forceinline__ void ldsm_x4(uint32_t* r, uint32_t addr) {
    asm volatile("ldmatrix.sync.aligned.m8n8.x4.shared.b16 {%0,%1,%2,%3}, [%4];"
                 : "=r"(r[0]), "=r"(r[1]), "=r"(r[2]), "=r"(r[3]) : "r"(addr));
}

__device__ __forceinline__ void mma_bf16(float* d, const uint32_t* a,
                                         const uint32_t* b) {
    asm volatile(
        "mma.sync.aligned.m16n8k16.row.col.f32.bf16.bf16.f32 "
        "{%0,%1,%2,%3}, {%4,%5,%6,%7}, {%8,%9}, {%0,%1,%2,%3};"
        : "+f"(d[0]), "+f"(d[1]), "+f"(d[2]), "+f"(d[3])
        : "r"(a[0]), "r"(a[1]), "r"(a[2]), "r"(a[3]), "r"(b[0]), "r"(b[1]));
}

// ---------------------------------------------------------------------------
// Kernel 1: tiled transpose x,label (B,N) -> (N,B)
// ---------------------------------------------------------------------------
__global__ __launch_bounds__(256) void transpose_kernel(
    const float* __restrict__ x, const float* __restrict__ label)
{
    __shared__ float tile[32][33];
    const float* src = blockIdx.z ? label : x;
    float* dst       = blockIdx.z ? g_lT  : g_xT;

    int c = blockIdx.x * 32 + threadIdx.x;
    int r = blockIdx.y * 32 + threadIdx.y;
#pragma unroll
    for (int j = 0; j < 32; j += 8)
        tile[threadIdx.y + j][threadIdx.x] = src[(size_t)(r + j) * N_DIM + c];
    __syncthreads();

    int c2 = blockIdx.y * 32 + threadIdx.x;
    int r2 = blockIdx.x * 32 + threadIdx.y;
#pragma unroll
    for (int j = 0; j < 32; j += 8)
        dst[(size_t)(r2 + j) * B_DIM + c2] = tile[threadIdx.x][threadIdx.y + j];
}

// ---------------------------------------------------------------------------
// Kernel 2: A[q*8192 + r] = relu( sum_j w0[j]*xT[adj[q][j]][r]
//                                + sum_j w1[j]*lT[adj[q][j]][r] + cb )
// written as bf16 hi/lo split pair (g_Ah, g_Al).
// ---------------------------------------------------------------------------
__global__ __launch_bounds__(256) void build_A_kernel(
    const int* __restrict__ adj,
    const float* __restrict__ conv_w,
    const float* __restrict__ conv_b)
{
    const int q = blockIdx.y;
    const int r = blockIdx.x * 1024 + threadIdx.x * 4;

    float w[8];
#pragma unroll
    for (int j = 0; j < 8; j++) w[j] = __ldg(&conv_w[j]);
    const float cb = __ldg(&conv_b[0]);

    const int c0 = __ldg(&adj[q * 4 + 0]);
    const int c1 = __ldg(&adj[q * 4 + 1]);
    const int c2 = __ldg(&adj[q * 4 + 2]);
    const int c3 = __ldg(&adj[q * 4 + 3]);

    float4 acc = make_float4(cb, cb, cb, cb);
#define ACC4(buf, col, wj)                                                    \
    {                                                                         \
        float4 v = *(const float4*)&buf[(size_t)(col) * B_DIM + r];           \
        acc.x = fmaf((wj), v.x, acc.x);                                       \
        acc.y = fmaf((wj), v.y, acc.y);                                       \
        acc.z = fmaf((wj), v.z, acc.z);                                       \
        acc.w = fmaf((wj), v.w, acc.w);                                       \
    }
    ACC4(g_xT, c0, w[0]); ACC4(g_xT, c1, w[1]);
    ACC4(g_xT, c2, w[2]); ACC4(g_xT, c3, w[3]);
    ACC4(g_lT, c0, w[4]); ACC4(g_lT, c1, w[5]);
    ACC4(g_lT, c2, w[6]); ACC4(g_lT, c3, w[7]);
#undef ACC4

    float a0 = fmaxf(acc.x, 0.f), a1 = fmaxf(acc.y, 0.f);
    float a2 = fmaxf(acc.z, 0.f), a3 = fmaxf(acc.w, 0.f);

    __nv_bfloat16 h0 = __float2bfloat16(a0), h1 = __float2bfloat16(a1);
    __nv_bfloat16 h2 = __float2bfloat16(a2), h3 = __float2bfloat16(a3);
    __nv_bfloat16 l0 = __float2bfloat16(a0 - __bfloat162float(h0));
    __nv_bfloat16 l1 = __float2bfloat16(a1 - __bfloat162float(h1));
    __nv_bfloat16 l2 = __float2bfloat16(a2 - __bfloat162float(h2));
    __nv_bfloat16 l3 = __float2bfloat16(a3 - __bfloat162float(h3));

    const size_t o = (size_t)q * B_DIM + r;
    __nv_bfloat162* ph = (__nv_bfloat162*)&g_Ah[o];
    __nv_bfloat162* pl = (__nv_bfloat162*)&g_Al[o];
    ph[0] = __nv_bfloat162(h0, h1); ph[1] = __nv_bfloat162(h2, h3);
    pl[0] = __nv_bfloat162(l0, l1); pl[1] = __nv_bfloat162(l2, l3);
}

// ---------------------------------------------------------------------------
// Kernel 3: split lin_w into bf16 hi/lo
// ---------------------------------------------------------------------------
__global__ __launch_bounds__(256) void split_W_kernel(const float* __restrict__ W)
{
    const size_t i = ((size_t)blockIdx.x * 256 + threadIdx.x) * 4;
    float4 v = __ldg((const float4*)(W + i));
    __nv_bfloat16 h0 = __float2bfloat16(v.x), h1 = __float2bfloat16(v.y);
    __nv_bfloat16 h2 = __float2bfloat16(v.z), h3 = __float2bfloat16(v.w);
    __nv_bfloat16 l0 = __float2bfloat16(v.x - __bfloat162float(h0));
    __nv_bfloat16 l1 = __float2bfloat16(v.y - __bfloat162float(h1));
    __nv_bfloat16 l2 = __float2bfloat16(v.z - __bfloat162float(h2));
    __nv_bfloat16 l3 = __float2bfloat16(v.w - __bfloat162float(h3));
    __nv_bfloat162* ph = (__nv_bfloat162*)&g_Wh[i];
    __nv_bfloat162* pl = (__nv_bfloat162*)&g_Wl[i];
    ph[0] = __nv_bfloat162(h0, h1); ph[1] = __nv_bfloat162(h2, h3);
    pl[0] = __nv_bfloat162(l0, l1); pl[1] = __nv_bfloat162(l2, l3);
}

// ---------------------------------------------------------------------------
// Kernel 4: mma.sync bf16 GEMM  C = A @ W^T + b   (M=8192, N=2048, K=2048)
// CTA 128x128, K-chunk 64 (SW128 rows), 2-stage cp.async pipeline,
// 8 warps (2 m x 4 n), warp tile 64x32, 3-term bf16 split.
// ---------------------------------------------------------------------------
static constexpr int BM = 128, BN = 128, BK = 64;
static constexpr int NSTEP = N_DIM / BK;               // 32
static constexpr uint32_t TILE_B  = BM * BK * 2;       // 16384 per matrix
static constexpr uint32_t STAGE_B = 4 * TILE_B;        // 65536 (Ah,Al,Wh,Wl)
static constexpr uint32_t GEMM_SMEM = 2 * STAGE_B;     // 131072

__device__ __forceinline__ void load_stage(uint32_t sbase, int stage,
                                           int m0, int n0, int k0, int tid)
{
    const uint32_t st = sbase + (uint32_t)stage * STAGE_B;
#pragma unroll
    for (int i = 0; i < 4; i++) {
        int idx = tid + i * 256;          // 0..1023
        int row = idx >> 3;               // 0..127
        int ch  = idx & 7;                // 16B chunk within 128B row
        uint32_t so = SW128((uint32_t)(row * 128 + ch * 16));
        size_t ga = (size_t)(m0 + row) * N_DIM + k0 + ch * 8;
        size_t gw = (size_t)(n0 + row) * N_DIM + k0 + ch * 8;
        cp16(st + 0 * TILE_B + so, g_Ah + ga);
        cp16(st + 1 * TILE_B + so, g_Al + ga);
        cp16(st + 2 * TILE_B + so, g_Wh + gw);
        cp16(st + 3 * TILE_B + so, g_Wl + gw);
    }
}

__global__ __launch_bounds__(256, 1) void gemm_mma_kernel(
    const float* __restrict__ bias, float* __restrict__ C)
{
    extern __shared__ char smem[];
    const uint32_t sbase = smem_u32(smem);
    const int tid  = threadIdx.x;
    const int wid  = tid >> 5;
    const int lane = tid & 31;
    const int n0 = blockIdx.x * BN;
    const int m0 = blockIdx.y * BM;

    const int warp_row = (wid >> 2) * 64;   // 0 or 64
    const int warp_col = (wid & 3) * 32;    // 0,32,64,96

    float acc[4][4][4] = {};                // [m frag][n frag][reg]

    load_stage(sbase, 0, m0, n0, 0, tid);  CP_COMMIT();
    load_stage(sbase, 1, m0, n0, BK, tid); CP_COMMIT();

    for (int it = 0; it < NSTEP; ++it) {
        if (it < NSTEP - 2) { CP_WAIT(1); } else { CP_WAIT(0); }
        __syncthreads();

        const uint32_t st = sbase + (uint32_t)(it & 1) * STAGE_B;
        const uint32_t chsel = (uint32_t)(lane >> 4);   // 0 or 1 (16B chunk)
#pragma unroll
        for (int ks = 0; ks < 4; ks++) {
            uint32_t ah[4][4], al[4][4], bh[4][2], bl[4][2];
            const int ch = ks * 2 + (int)chsel;
#pragma unroll
            for (int mf = 0; mf < 4; mf++) {
                int row = warp_row + mf * 16 + (lane & 15);
                uint32_t so = SW128((uint32_t)(row * 128 + ch * 16));
                ldsm_x4(ah[mf], st + 0 * TILE_B + so);
                ldsm_x4(al[mf], st + 1 * TILE_B + so);
            }
#pragma unroll
            for (int g = 0; g < 2; g++) {
                int n = warp_col + g * 16 + (lane & 15);
                uint32_t so = SW128((uint32_t)(n * 128 + ch * 16));
                uint32_t t[4];
                ldsm_x4(t, st + 2 * TILE_B + so);
                bh[g * 2 + 0][0] = t[0]; bh[g * 2 + 0][1] = t[2];
                bh[g * 2 + 1][0] = t[1]; bh[g * 2 + 1][1] = t[3];
                ldsm_x4(t, st + 3 * TILE_B + so);
                bl[g * 2 + 0][0] = t[0]; bl[g * 2 + 0][1] = t[2];
                bl[g * 2 + 1][0] = t[1]; bl[g * 2 + 1][1] = t[3];
            }
#pragma unroll
            for (int mf = 0; mf < 4; mf++)
#pragma unroll
                for (int nf = 0; nf < 4; nf++) {
                    mma_bf16(acc[mf][nf], ah[mf], bh[nf]);
                    mma_bf16(acc[mf][nf], ah[mf], bl[nf]);
                    mma_bf16(acc[mf][nf], al[mf], bh[nf]);
                }
        }
        __syncthreads();

        if (it + 2 < NSTEP) {
            load_stage(sbase, it & 1, m0, n0, (it + 2) * BK, tid);
            CP_COMMIT();
        }
    }

    // ----- epilogue: add bias, write C -----
    const int r_base = m0 + warp_row + (lane >> 2);
    const int c_base = n0 + warp_col + (lane & 3) * 2;
#pragma unroll
    for (int mf = 0; mf < 4; mf++)
#pragma unroll
        for (int nf = 0; nf < 4; nf++) {
            int r = r_base + mf * 16;
            int c = c_base + nf * 8;
            float b0 = __ldg(&bias[c]), b1 = __ldg(&bias[c + 1]);
            float2 v0 = make_float2(acc[mf][nf][0] + b0, acc[mf][nf][1] + b1);
            float2 v1 = make_float2(acc[mf][nf][2] + b0, acc[mf][nf][3] + b1);
            *(float2*)&C[(size_t)r * N_DIM + c]       = v0;
            *(float2*)&C[(size_t)(r + 8) * N_DIM + c] = v1;
        }
}

// ---------------------------------------------------------------------------
extern "C" void kernel_launch(void* const* d_in, const int* in_sizes, int n_in,
                              void* d_out, int out_size)
{
    const float* x      = (const float*)d_in[0];
    const float* label  = (const float*)d_in[1];
    const int*   adj    = (const int*)  d_in[2];
    const float* conv_w = (const float*)d_in[3];
    const float* conv_b = (const float*)d_in[4];
    const float* lin_w  = (const float*)d_in[5];
    const float* lin_b  = (const float*)d_in[6];
    float* out = (float*)d_out;

    {   // 1) transpose
        dim3 grid(N_DIM / 32, B_DIM / 32, 2);
        dim3 block(32, 8, 1);
        transpose_kernel<<<grid, block>>>(x, label);
    }
    {   // 2) build A (bf16 hi/lo)
        dim3 grid(B_DIM / (256 * 4), N_DIM, 1);
        build_A_kernel<<<grid, 256>>>(adj, conv_w, conv_b);
    }
    {   // 3) split W (bf16 hi/lo)
        split_W_kernel<<<(N_DIM * N_DIM / 4) / 256, 256>>>(lin_w);
    }
    {   // 4) tensor-core GEMM via mma.sync
        cudaFuncSetAttribute(gemm_mma_kernel,
                             cudaFuncAttributeMaxDynamicSharedMemorySize,
                             GEMM_SMEM);
        dim3 grid(N_DIM / BN, B_DIM / BM, 1);
        gemm_mma_kernel<<<grid, 256, GEMM_SMEM>>>(lin_b, out);
    }
}

// round 4
// speedup vs baseline: 3.6509x; 1.3611x over previous
#include <cuda_runtime.h>
#include <cuda_fp16.h>
#include <cstdint>

static constexpr int B_DIM = 8192;   // batch (GEMM M)
static constexpr int N_DIM = 2048;   // nodes / features (GEMM N and K)

// W is scaled by 64 before the fp16 hi/lo split so that Wl stays normal.
static constexpr float W_SCALE = 64.0f;
static constexpr float W_INV_SCALE = 1.0f / 64.0f;

// ---------------- scratch (device globals; allocation-free rule) ------------
__device__ float g_xT[(size_t)N_DIM * B_DIM];        // x^T  (N, B)
__device__ float g_lT[(size_t)N_DIM * B_DIM];        // label^T (N, B)
__device__ __half g_Af[(size_t)B_DIM * N_DIM];       // A fp16 (8192 x 2048)
__device__ __half g_Wh[(size_t)N_DIM * N_DIM];       // 64*W hi
__device__ __half g_Wl[(size_t)N_DIM * N_DIM];       // 64*W lo

#define SW128(x) ((x) ^ (((x) >> 3) & 0x70))

// ---------------------------- PTX helpers (sm_80+ only) ---------------------
__device__ __forceinline__ uint32_t smem_u32(const void* p) {
    uint32_t a;
    asm("{ .reg .u64 t; cvta.to.shared.u64 t, %1; cvt.u32.u64 %0, t; }"
        : "=r"(a) : "l"(p));
    return a;
}

__device__ __forceinline__ void cp16(uint32_t saddr, const void* gaddr) {
    asm volatile("cp.async.cg.shared.global [%0], [%1], 16;"
                 :: "r"(saddr), "l"(gaddr) : "memory");
}
#define CP_COMMIT() asm volatile("cp.async.commit_group;" ::: "memory")
#define CP_WAIT(n)  asm volatile("cp.async.wait_group %0;" :: "n"(n) : "memory")

__device__ __forceinline__ void ldsm_x4(uint32_t* r, uint32_t addr) {
    asm volatile("ldmatrix.sync.aligned.m8n8.x4.shared.b16 {%0,%1,%2,%3}, [%4];"
                 : "=r"(r[0]), "=r"(r[1]), "=r"(r[2]), "=r"(r[3]) : "r"(addr));
}

__device__ __forceinline__ void mma_fp16(float* d, const uint32_t* a,
                                         const uint32_t* b) {
    asm volatile(
        "mma.sync.aligned.m16n8k16.row.col.f32.f16.f16.f32 "
        "{%0,%1,%2,%3}, {%4,%5,%6,%7}, {%8,%9}, {%0,%1,%2,%3};"
        : "+f"(d[0]), "+f"(d[1]), "+f"(d[2]), "+f"(d[3])
        : "r"(a[0]), "r"(a[1]), "r"(a[2]), "r"(a[3]), "r"(b[0]), "r"(b[1]));
}

// ---------------------------------------------------------------------------
// Kernel 1: tiled transpose x,label (B,N) -> (N,B)
// ---------------------------------------------------------------------------
__global__ __launch_bounds__(256) void transpose_kernel(
    const float* __restrict__ x, const float* __restrict__ label)
{
    __shared__ float tile[32][33];
    const float* src = blockIdx.z ? label : x;
    float* dst       = blockIdx.z ? g_lT  : g_xT;

    int c = blockIdx.x * 32 + threadIdx.x;
    int r = blockIdx.y * 32 + threadIdx.y;
#pragma unroll
    for (int j = 0; j < 32; j += 8)
        tile[threadIdx.y + j][threadIdx.x] = src[(size_t)(r + j) * N_DIM + c];
    __syncthreads();

    int c2 = blockIdx.y * 32 + threadIdx.x;
    int r2 = blockIdx.x * 32 + threadIdx.y;
#pragma unroll
    for (int j = 0; j < 32; j += 8)
        dst[(size_t)(r2 + j) * B_DIM + c2] = tile[threadIdx.x][threadIdx.y + j];
}

// ---------------------------------------------------------------------------
// Kernel 2: A[q*8192 + r] = relu( sum_j w0[j]*xT[adj[q][j]][r]
//                                + sum_j w1[j]*lT[adj[q][j]][r] + cb )
// written as fp16.
// ---------------------------------------------------------------------------
__global__ __launch_bounds__(256) void build_A_kernel(
    const int* __restrict__ adj,
    const float* __restrict__ conv_w,
    const float* __restrict__ conv_b)
{
    const int q = blockIdx.y;
    const int r = blockIdx.x * 1024 + threadIdx.x * 4;

    float w[8];
#pragma unroll
    for (int j = 0; j < 8; j++) w[j] = __ldg(&conv_w[j]);
    const float cb = __ldg(&conv_b[0]);

    const int c0 = __ldg(&adj[q * 4 + 0]);
    const int c1 = __ldg(&adj[q * 4 + 1]);
    const int c2 = __ldg(&adj[q * 4 + 2]);
    const int c3 = __ldg(&adj[q * 4 + 3]);

    float4 acc = make_float4(cb, cb, cb, cb);
#define ACC4(buf, col, wj)                                                    \
    {                                                                         \
        float4 v = *(const float4*)&buf[(size_t)(col) * B_DIM + r];           \
        acc.x = fmaf((wj), v.x, acc.x);                                       \
        acc.y = fmaf((wj), v.y, acc.y);                                       \
        acc.z = fmaf((wj), v.z, acc.z);                                       \
        acc.w = fmaf((wj), v.w, acc.w);                                       \
    }
    ACC4(g_xT, c0, w[0]); ACC4(g_xT, c1, w[1]);
    ACC4(g_xT, c2, w[2]); ACC4(g_xT, c3, w[3]);
    ACC4(g_lT, c0, w[4]); ACC4(g_lT, c1, w[5]);
    ACC4(g_lT, c2, w[6]); ACC4(g_lT, c3, w[7]);
#undef ACC4

    __half2 h01 = __floats2half2_rn(fmaxf(acc.x, 0.f), fmaxf(acc.y, 0.f));
    __half2 h23 = __floats2half2_rn(fmaxf(acc.z, 0.f), fmaxf(acc.w, 0.f));

    __half2* ph = (__half2*)&g_Af[(size_t)q * B_DIM + r];
    ph[0] = h01; ph[1] = h23;
}

// ---------------------------------------------------------------------------
// Kernel 3: split 64*lin_w into fp16 hi/lo
// ---------------------------------------------------------------------------
__global__ __launch_bounds__(256) void split_W_kernel(const float* __restrict__ W)
{
    const size_t i = ((size_t)blockIdx.x * 256 + threadIdx.x) * 4;
    float4 v = __ldg((const float4*)(W + i));
    float s0 = v.x * W_SCALE, s1 = v.y * W_SCALE;
    float s2 = v.z * W_SCALE, s3 = v.w * W_SCALE;
    __half h0 = __float2half_rn(s0), h1 = __float2half_rn(s1);
    __half h2 = __float2half_rn(s2), h3 = __float2half_rn(s3);
    __half l0 = __float2half_rn(s0 - __half2float(h0));
    __half l1 = __float2half_rn(s1 - __half2float(h1));
    __half l2 = __float2half_rn(s2 - __half2float(h2));
    __half l3 = __float2half_rn(s3 - __half2float(h3));
    __half2* ph = (__half2*)&g_Wh[i];
    __half2* pl = (__half2*)&g_Wl[i];
    ph[0] = __half2(h0, h1); ph[1] = __half2(h2, h3);
    pl[0] = __half2(l0, l1); pl[1] = __half2(l2, l3);
}

// ---------------------------------------------------------------------------
// Kernel 4: mma.sync fp16 GEMM  C = (Af @ (Wh+Wl)^T)/64 + b
// M=8192, N=2048, K=2048. CTA 128x128, BK=64, 3-stage cp.async pipeline,
// 8 warps (2m x 4n), warp tile 64x32, 2-term fp16 split, frag double buffer.
// ---------------------------------------------------------------------------
static constexpr int BM = 128, BN = 128, BK = 64;
static constexpr int NSTEP = N_DIM / BK;               // 32
static constexpr int NSTAGE = 3;
static constexpr uint32_t TILE_B  = BM * BK * 2;       // 16384 per matrix
static constexpr uint32_t STAGE_B = 3 * TILE_B;        // 49152 (Af, Wh, Wl)
static constexpr uint32_t GEMM_SMEM = NSTAGE * STAGE_B; // 147456

struct Frags {
    uint32_t a[4][4];
    uint32_t bh[4][2];
    uint32_t bl[4][2];
};

__device__ __forceinline__ void load_stage(uint32_t sbase, int stage,
                                           int m0, int n0, int k0, int tid)
{
    const uint32_t st = sbase + (uint32_t)stage * STAGE_B;
#pragma unroll
    for (int i = 0; i < 4; i++) {
        int idx = tid + i * 256;          // 0..1023
        int row = idx >> 3;               // 0..127
        int ch  = idx & 7;                // 16B chunk within 128B row
        uint32_t so = SW128((uint32_t)(row * 128 + ch * 16));
        size_t ga = (size_t)(m0 + row) * N_DIM + k0 + ch * 8;
        size_t gw = (size_t)(n0 + row) * N_DIM + k0 + ch * 8;
        cp16(st + 0 * TILE_B + so, g_Af + ga);
        cp16(st + 1 * TILE_B + so, g_Wh + gw);
        cp16(st + 2 * TILE_B + so, g_Wl + gw);
    }
}

__device__ __forceinline__ void ld_frags(Frags& f, uint32_t st, int ks,
                                         int lane, int warp_row, int warp_col)
{
    const int ch = ks * 2 + (lane >> 4);
#pragma unroll
    for (int mf = 0; mf < 4; mf++) {
        int row = warp_row + mf * 16 + (lane & 15);
        uint32_t so = SW128((uint32_t)(row * 128 + ch * 16));
        ldsm_x4(f.a[mf], st + 0 * TILE_B + so);
    }
#pragma unroll
    for (int g = 0; g < 2; g++) {
        int n = warp_col + g * 16 + (lane & 15);
        uint32_t so = SW128((uint32_t)(n * 128 + ch * 16));
        uint32_t t[4];
        ldsm_x4(t, st + 1 * TILE_B + so);
        f.bh[g * 2 + 0][0] = t[0]; f.bh[g * 2 + 0][1] = t[2];
        f.bh[g * 2 + 1][0] = t[1]; f.bh[g * 2 + 1][1] = t[3];
        ldsm_x4(t, st + 2 * TILE_B + so);
        f.bl[g * 2 + 0][0] = t[0]; f.bl[g * 2 + 0][1] = t[2];
        f.bl[g * 2 + 1][0] = t[1]; f.bl[g * 2 + 1][1] = t[3];
    }
}

__global__ __launch_bounds__(256, 1) void gemm_mma_kernel(
    const float* __restrict__ bias, float* __restrict__ C)
{
    extern __shared__ char smem[];
    const uint32_t sbase = smem_u32(smem);
    const int tid  = threadIdx.x;
    const int wid  = tid >> 5;
    const int lane = tid & 31;
    const int n0 = blockIdx.x * BN;
    const int m0 = blockIdx.y * BM;

    const int warp_row = (wid >> 2) * 64;   // 0 or 64
    const int warp_col = (wid & 3) * 32;    // 0,32,64,96

    float acc[4][4][4] = {};                // [m frag][n frag][reg]

    load_stage(sbase, 0, m0, n0, 0, tid);  CP_COMMIT();
    load_stage(sbase, 1, m0, n0, BK, tid); CP_COMMIT();

    for (int it = 0; it < NSTEP; ++it) {
        if (it + 1 < NSTEP) { CP_WAIT(1); } else { CP_WAIT(0); }
        __syncthreads();

        // issue next stage loads before computing (overlaps this iteration)
        if (it + 2 < NSTEP) {
            load_stage(sbase, (it + 2) % NSTAGE, m0, n0, (it + 2) * BK, tid);
            CP_COMMIT();
        }

        const uint32_t st = sbase + (uint32_t)(it % NSTAGE) * STAGE_B;

        Frags f0, f1;
        ld_frags(f0, st, 0, lane, warp_row, warp_col);
#pragma unroll
        for (int ks = 0; ks < 4; ks++) {
            Frags& cur = (ks & 1) ? f1 : f0;
            Frags& nxt = (ks & 1) ? f0 : f1;
            if (ks < 3) ld_frags(nxt, st, ks + 1, lane, warp_row, warp_col);
#pragma unroll
            for (int mf = 0; mf < 4; mf++)
#pragma unroll
                for (int nf = 0; nf < 4; nf++) {
                    mma_fp16(acc[mf][nf], cur.a[mf], cur.bh[nf]);
                    mma_fp16(acc[mf][nf], cur.a[mf], cur.bl[nf]);
                }
        }
    }

    // ----- epilogue: scale by 1/64, add bias, write C -----
    const int r_base = m0 + warp_row + (lane >> 2);
    const int c_base = n0 + warp_col + (lane & 3) * 2;
#pragma unroll
    for (int mf = 0; mf < 4; mf++)
#pragma unroll
        for (int nf = 0; nf < 4; nf++) {
            int r = r_base + mf * 16;
            int c = c_base + nf * 8;
            float b0 = __ldg(&bias[c]), b1 = __ldg(&bias[c + 1]);
            float2 v0 = make_float2(fmaf(acc[mf][nf][0], W_INV_SCALE, b0),
                                    fmaf(acc[mf][nf][1], W_INV_SCALE, b1));
            float2 v1 = make_float2(fmaf(acc[mf][nf][2], W_INV_SCALE, b0),
                                    fmaf(acc[mf][nf][3], W_INV_SCALE, b1));
            *(float2*)&C[(size_t)r * N_DIM + c]       = v0;
            *(float2*)&C[(size_t)(r + 8) * N_DIM + c] = v1;
        }
}

// ---------------------------------------------------------------------------
extern "C" void kernel_launch(void* const* d_in, const int* in_sizes, int n_in,
                              void* d_out, int out_size)
{
    const float* x      = (const float*)d_in[0];
    const float* label  = (const float*)d_in[1];
    const int*   adj    = (const int*)  d_in[2];
    const float* conv_w = (const float*)d_in[3];
    const float* conv_b = (const float*)d_in[4];
    const float* lin_w  = (const float*)d_in[5];
    const float* lin_b  = (const float*)d_in[6];
    float* out = (float*)d_out;

    {   // 1) transpose
        dim3 grid(N_DIM / 32, B_DIM / 32, 2);
        dim3 block(32, 8, 1);
        transpose_kernel<<<grid, block>>>(x, label);
    }
    {   // 2) build A (fp16)
        dim3 grid(B_DIM / (256 * 4), N_DIM, 1);
        build_A_kernel<<<grid, 256>>>(adj, conv_w, conv_b);
    }
    {   // 3) split 64*W (fp16 hi/lo)
        split_W_kernel<<<(N_DIM * N_DIM / 4) / 256, 256>>>(lin_w);
    }
    {   // 4) tensor-core GEMM via mma.sync (2-term fp16)
        cudaFuncSetAttribute(gemm_mma_kernel,
                             cudaFuncAttributeMaxDynamicSharedMemorySize,
                             GEMM_SMEM);
        dim3 grid(N_DIM / BN, B_DIM / BM, 1);
        gemm_mma_kernel<<<grid, 256, GEMM_SMEM>>>(lin_b, out);
    }
}

// round 5
// speedup vs baseline: 3.8132x; 1.0444x over previous
#include <cuda_runtime.h>
#include <cuda_fp16.h>
#include <cstdint>

static constexpr int B_DIM = 8192;   // batch (GEMM M)
static constexpr int N_DIM = 2048;   // nodes / features (GEMM N and K)

// W is scaled by 64 before the fp16 hi/lo split so that Wl stays normal.
static constexpr float W_SCALE = 64.0f;
static constexpr float W_INV_SCALE = 1.0f / 64.0f;

// ---------------- scratch (device globals; allocation-free rule) ------------
__device__ float g_xT[(size_t)N_DIM * B_DIM];        // x^T  (N, B)
__device__ float g_lT[(size_t)N_DIM * B_DIM];        // label^T (N, B)
__device__ __half g_Af[(size_t)B_DIM * N_DIM];       // A fp16 (8192 x 2048)
__device__ __half g_Wh[(size_t)N_DIM * N_DIM];       // 64*W hi
__device__ __half g_Wl[(size_t)N_DIM * N_DIM];       // 64*W lo

#define SW64(x) ((x) ^ (((x) >> 3) & 0x30))

// ---------------------------- PTX helpers (sm_80+ only) ---------------------
__device__ __forceinline__ uint32_t smem_u32(const void* p) {
    uint32_t a;
    asm("{ .reg .u64 t; cvta.to.shared.u64 t, %1; cvt.u32.u64 %0, t; }"
        : "=r"(a) : "l"(p));
    return a;
}

__device__ __forceinline__ void cp16(uint32_t saddr, const void* gaddr) {
    asm volatile("cp.async.cg.shared.global [%0], [%1], 16;"
                 :: "r"(saddr), "l"(gaddr) : "memory");
}
#define CP_COMMIT() asm volatile("cp.async.commit_group;" ::: "memory")
#define CP_WAIT(n)  asm volatile("cp.async.wait_group %0;" :: "n"(n) : "memory")

__device__ __forceinline__ void ldsm_x4(uint32_t* r, uint32_t addr) {
    asm volatile("ldmatrix.sync.aligned.m8n8.x4.shared.b16 {%0,%1,%2,%3}, [%4];"
                 : "=r"(r[0]), "=r"(r[1]), "=r"(r[2]), "=r"(r[3]) : "r"(addr));
}

__device__ __forceinline__ void mma_fp16(float* d, const uint32_t* a,
                                         const uint32_t* b) {
    asm volatile(
        "mma.sync.aligned.m16n8k16.row.col.f32.f16.f16.f32 "
        "{%0,%1,%2,%3}, {%4,%5,%6,%7}, {%8,%9}, {%0,%1,%2,%3};"
        : "+f"(d[0]), "+f"(d[1]), "+f"(d[2]), "+f"(d[3])
        : "r"(a[0]), "r"(a[1]), "r"(a[2]), "r"(a[3]), "r"(b[0]), "r"(b[1]));
}

// ---------------------------------------------------------------------------
// Kernel 1: tiled transpose x,label (B,N) -> (N,B)
// ---------------------------------------------------------------------------
__global__ __launch_bounds__(256) void transpose_kernel(
    const float* __restrict__ x, const float* __restrict__ label)
{
    __shared__ float tile[32][33];
    const float* src = blockIdx.z ? label : x;
    float* dst       = blockIdx.z ? g_lT  : g_xT;

    int c = blockIdx.x * 32 + threadIdx.x;
    int r = blockIdx.y * 32 + threadIdx.y;
#pragma unroll
    for (int j = 0; j < 32; j += 8)
        tile[threadIdx.y + j][threadIdx.x] = src[(size_t)(r + j) * N_DIM + c];
    __syncthreads();

    int c2 = blockIdx.y * 32 + threadIdx.x;
    int r2 = blockIdx.x * 32 + threadIdx.y;
#pragma unroll
    for (int j = 0; j < 32; j += 8)
        dst[(size_t)(r2 + j) * B_DIM + c2] = tile[threadIdx.x][threadIdx.y + j];
}

// ---------------------------------------------------------------------------
// Kernel 2: A[q*8192 + r] = relu( sum_j w0[j]*xT[adj[q][j]][r]
//                                + sum_j w1[j]*lT[adj[q][j]][r] + cb ), fp16.
// ---------------------------------------------------------------------------
__global__ __launch_bounds__(256) void build_A_kernel(
    const int* __restrict__ adj,
    const float* __restrict__ conv_w,
    const float* __restrict__ conv_b)
{
    const int q = blockIdx.y;
    const int r = blockIdx.x * 1024 + threadIdx.x * 4;

    float w[8];
#pragma unroll
    for (int j = 0; j < 8; j++) w[j] = __ldg(&conv_w[j]);
    const float cb = __ldg(&conv_b[0]);

    const int c0 = __ldg(&adj[q * 4 + 0]);
    const int c1 = __ldg(&adj[q * 4 + 1]);
    const int c2 = __ldg(&adj[q * 4 + 2]);
    const int c3 = __ldg(&adj[q * 4 + 3]);

    float4 acc = make_float4(cb, cb, cb, cb);
#define ACC4(buf, col, wj)                                                    \
    {                                                                         \
        float4 v = *(const float4*)&buf[(size_t)(col) * B_DIM + r];           \
        acc.x = fmaf((wj), v.x, acc.x);                                       \
        acc.y = fmaf((wj), v.y, acc.y);                                       \
        acc.z = fmaf((wj), v.z, acc.z);                                       \
        acc.w = fmaf((wj), v.w, acc.w);                                       \
    }
    ACC4(g_xT, c0, w[0]); ACC4(g_xT, c1, w[1]);
    ACC4(g_xT, c2, w[2]); ACC4(g_xT, c3, w[3]);
    ACC4(g_lT, c0, w[4]); ACC4(g_lT, c1, w[5]);
    ACC4(g_lT, c2, w[6]); ACC4(g_lT, c3, w[7]);
#undef ACC4

    __half2 h01 = __floats2half2_rn(fmaxf(acc.x, 0.f), fmaxf(acc.y, 0.f));
    __half2 h23 = __floats2half2_rn(fmaxf(acc.z, 0.f), fmaxf(acc.w, 0.f));

    __half2* ph = (__half2*)&g_Af[(size_t)q * B_DIM + r];
    ph[0] = h01; ph[1] = h23;
}

// ---------------------------------------------------------------------------
// Kernel 3: split 64*lin_w into fp16 hi/lo
// ---------------------------------------------------------------------------
__global__ __launch_bounds__(256) void split_W_kernel(const float* __restrict__ W)
{
    const size_t i = ((size_t)blockIdx.x * 256 + threadIdx.x) * 4;
    float4 v = __ldg((const float4*)(W + i));
    float s0 = v.x * W_SCALE, s1 = v.y * W_SCALE;
    float s2 = v.z * W_SCALE, s3 = v.w * W_SCALE;
    __half h0 = __float2half_rn(s0), h1 = __float2half_rn(s1);
    __half h2 = __float2half_rn(s2), h3 = __float2half_rn(s3);
    __half l0 = __float2half_rn(s0 - __half2float(h0));
    __half l1 = __float2half_rn(s1 - __half2float(h1));
    __half l2 = __float2half_rn(s2 - __half2float(h2));
    __half l3 = __float2half_rn(s3 - __half2float(h3));
    __half2* ph = (__half2*)&g_Wh[i];
    __half2* pl = (__half2*)&g_Wl[i];
    ph[0] = __half2(h0, h1); ph[1] = __half2(h2, h3);
    pl[0] = __half2(l0, l1); pl[1] = __half2(l2, l3);
}

// ---------------------------------------------------------------------------
// Kernel 4: mma.sync fp16 GEMM  C = (Af @ (Wh+Wl)^T)/64 + b
// M=8192, N=2048, K=2048. CTA 128x128, BK=32 (SW64 rows), 4-stage cp.async,
// 8 warps (2m x 4n), warp tile 64x32, 2 CTAs/SM for bubble hiding.
// ---------------------------------------------------------------------------
static constexpr int BM = 128, BN = 128, BK = 32;
static constexpr int NSTEP = N_DIM / BK;                 // 64
static constexpr int NSTAGE = 4;
static constexpr uint32_t TILE_B  = BM * BK * 2;         // 8192 per matrix
static constexpr uint32_t STAGE_B = 3 * TILE_B;          // 24576 (Af, Wh, Wl)
static constexpr uint32_t GEMM_SMEM = NSTAGE * STAGE_B;  // 98304

__device__ __forceinline__ void load_stage(uint32_t sbase, int stage,
                                           int m0, int n0, int k0, int tid)
{
    const uint32_t st = sbase + (uint32_t)stage * STAGE_B;
#pragma unroll
    for (int i = 0; i < 2; i++) {
        int idx = tid + i * 256;          // 0..511
        int row = idx >> 2;               // 0..127
        int ch  = idx & 3;                // 16B chunk within 64B row
        uint32_t so = SW64((uint32_t)(row * 64 + ch * 16));
        size_t ga = (size_t)(m0 + row) * N_DIM + k0 + ch * 8;
        size_t gw = (size_t)(n0 + row) * N_DIM + k0 + ch * 8;
        cp16(st + 0 * TILE_B + so, g_Af + ga);
        cp16(st + 1 * TILE_B + so, g_Wh + gw);
        cp16(st + 2 * TILE_B + so, g_Wl + gw);
    }
}

__global__ __launch_bounds__(256, 2) void gemm_mma_kernel(
    const float* __restrict__ bias, float* __restrict__ C)
{
    extern __shared__ char smem[];
    const uint32_t sbase = smem_u32(smem);
    const int tid  = threadIdx.x;
    const int wid  = tid >> 5;
    const int lane = tid & 31;
    const int n0 = blockIdx.x * BN;
    const int m0 = blockIdx.y * BM;

    const int warp_row = (wid >> 2) * 64;   // 0 or 64
    const int warp_col = (wid & 3) * 32;    // 0,32,64,96

    float acc[4][4][4] = {};                // [m frag][n frag][reg]

    load_stage(sbase, 0, m0, n0, 0,      tid); CP_COMMIT();
    load_stage(sbase, 1, m0, n0, BK,     tid); CP_COMMIT();
    load_stage(sbase, 2, m0, n0, 2 * BK, tid); CP_COMMIT();

    for (int it = 0; it < NSTEP; ++it) {
        if (it + 2 < NSTEP)      { CP_WAIT(2); }
        else if (it + 1 < NSTEP) { CP_WAIT(1); }
        else                     { CP_WAIT(0); }
        __syncthreads();

        if (it + 3 < NSTEP) {
            load_stage(sbase, (it + 3) % NSTAGE, m0, n0, (it + 3) * BK, tid);
            CP_COMMIT();
        }

        const uint32_t st = sbase + (uint32_t)(it % NSTAGE) * STAGE_B;
#pragma unroll
        for (int ks = 0; ks < 2; ks++) {
            const int ch = ks * 2 + (lane >> 4);     // 16B chunk 0..3
            uint32_t a[4][4], bh[4][2], bl[4][2];
#pragma unroll
            for (int mf = 0; mf < 4; mf++) {
                int row = warp_row + mf * 16 + (lane & 15);
                uint32_t so = SW64((uint32_t)(row * 64 + ch * 16));
                ldsm_x4(a[mf], st + 0 * TILE_B + so);
            }
#pragma unroll
            for (int g = 0; g < 2; g++) {
                int n = warp_col + g * 16 + (lane & 15);
                uint32_t so = SW64((uint32_t)(n * 64 + ch * 16));
                uint32_t t[4];
                ldsm_x4(t, st + 1 * TILE_B + so);
                bh[g * 2 + 0][0] = t[0]; bh[g * 2 + 0][1] = t[2];
                bh[g * 2 + 1][0] = t[1]; bh[g * 2 + 1][1] = t[3];
                ldsm_x4(t, st + 2 * TILE_B + so);
                bl[g * 2 + 0][0] = t[0]; bl[g * 2 + 0][1] = t[2];
                bl[g * 2 + 1][0] = t[1]; bl[g * 2 + 1][1] = t[3];
            }
#pragma unroll
            for (int mf = 0; mf < 4; mf++)
#pragma unroll
                for (int nf = 0; nf < 4; nf++) {
                    mma_fp16(acc[mf][nf], a[mf], bh[nf]);
                    mma_fp16(acc[mf][nf], a[mf], bl[nf]);
                }
        }
        __syncthreads();
    }

    // ----- epilogue: scale by 1/64, add bias, write C -----
    const int r_base = m0 + warp_row + (lane >> 2);
    const int c_base = n0 + warp_col + (lane & 3) * 2;
#pragma unroll
    for (int mf = 0; mf < 4; mf++)
#pragma unroll
        for (int nf = 0; nf < 4; nf++) {
            int r = r_base + mf * 16;
            int c = c_base + nf * 8;
            float b0 = __ldg(&bias[c]), b1 = __ldg(&bias[c + 1]);
            float2 v0 = make_float2(fmaf(acc[mf][nf][0], W_INV_SCALE, b0),
                                    fmaf(acc[mf][nf][1], W_INV_SCALE, b1));
            float2 v1 = make_float2(fmaf(acc[mf][nf][2], W_INV_SCALE, b0),
                                    fmaf(acc[mf][nf][3], W_INV_SCALE, b1));
            *(float2*)&C[(size_t)r * N_DIM + c]       = v0;
            *(float2*)&C[(size_t)(r + 8) * N_DIM + c] = v1;
        }
}

// ---------------------------------------------------------------------------
extern "C" void kernel_launch(void* const* d_in, const int* in_sizes, int n_in,
                              void* d_out, int out_size)
{
    const float* x      = (const float*)d_in[0];
    const float* label  = (const float*)d_in[1];
    const int*   adj    = (const int*)  d_in[2];
    const float* conv_w = (const float*)d_in[3];
    const float* conv_b = (const float*)d_in[4];
    const float* lin_w  = (const float*)d_in[5];
    const float* lin_b  = (const float*)d_in[6];
    float* out = (float*)d_out;

    {   // 1) transpose
        dim3 grid(N_DIM / 32, B_DIM / 32, 2);
        dim3 block(32, 8, 1);
        transpose_kernel<<<grid, block>>>(x, label);
    }
    {   // 2) build A (fp16)
        dim3 grid(B_DIM / (256 * 4), N_DIM, 1);
        build_A_kernel<<<grid, 256>>>(adj, conv_w, conv_b);
    }
    {   // 3) split 64*W (fp16 hi/lo)
        split_W_kernel<<<(N_DIM * N_DIM / 4) / 256, 256>>>(lin_w);
    }
    {   // 4) tensor-core GEMM via mma.sync (2-term fp16, 2 CTAs/SM)
        cudaFuncSetAttribute(gemm_mma_kernel,
                             cudaFuncAttributeMaxDynamicSharedMemorySize,
                             GEMM_SMEM);
        dim3 grid(N_DIM / BN, B_DIM / BM, 1);
        gemm_mma_kernel<<<grid, 256, GEMM_SMEM>>>(lin_b, out);
    }
}

// round 6
// speedup vs baseline: 6.3168x; 1.6566x over previous
#include <cuda_runtime.h>
#include <cuda_fp16.h>
#include <cstdint>

static constexpr int B_DIM = 8192;   // batch (GEMM M)
static constexpr int N_DIM = 2048;   // nodes / features (GEMM N and K)

// ---------------- scratch (device globals; allocation-free rule) ------------
__device__ __half g_xTh[(size_t)N_DIM * B_DIM];      // x^T  (N, B) fp16
__device__ __half g_lTh[(size_t)N_DIM * B_DIM];      // label^T (N, B) fp16
__device__ __half g_Af[(size_t)B_DIM * N_DIM];       // A fp16 (8192 x 2048)
__device__ __half g_Wf[(size_t)N_DIM * N_DIM];       // W fp16

#define SW64(x) ((x) ^ (((x) >> 3) & 0x30))

// ---------------------------- PTX helpers (sm_80+ only) ---------------------
__device__ __forceinline__ uint32_t smem_u32(const void* p) {
    uint32_t a;
    asm("{ .reg .u64 t; cvta.to.shared.u64 t, %1; cvt.u32.u64 %0, t; }"
        : "=r"(a) : "l"(p));
    return a;
}

__device__ __forceinline__ void cp16(uint32_t saddr, const void* gaddr) {
    asm volatile("cp.async.cg.shared.global [%0], [%1], 16;"
                 :: "r"(saddr), "l"(gaddr) : "memory");
}
#define CP_COMMIT() asm volatile("cp.async.commit_group;" ::: "memory")
#define CP_WAIT(n)  asm volatile("cp.async.wait_group %0;" :: "n"(n) : "memory")

__device__ __forceinline__ void ldsm_x4(uint32_t* r, uint32_t addr) {
    asm volatile("ldmatrix.sync.aligned.m8n8.x4.shared.b16 {%0,%1,%2,%3}, [%4];"
                 : "=r"(r[0]), "=r"(r[1]), "=r"(r[2]), "=r"(r[3]) : "r"(addr));
}

__device__ __forceinline__ void mma_fp16(float* d, const uint32_t* a,
                                         const uint32_t* b) {
    asm volatile(
        "mma.sync.aligned.m16n8k16.row.col.f32.f16.f16.f32 "
        "{%0,%1,%2,%3}, {%4,%5,%6,%7}, {%8,%9}, {%0,%1,%2,%3};"
        : "+f"(d[0]), "+f"(d[1]), "+f"(d[2]), "+f"(d[3])
        : "r"(a[0]), "r"(a[1]), "r"(a[2]), "r"(a[3]), "r"(b[0]), "r"(b[1]));
}

// ---------------------------------------------------------------------------
// Kernel 1: tiled transpose x,label (B,N) fp32 -> (N,B) fp16
// ---------------------------------------------------------------------------
__global__ __launch_bounds__(256) void transpose_kernel(
    const float* __restrict__ x, const float* __restrict__ label)
{
    __shared__ float tile[32][33];   // [node_local][batch_local]
    const float* src = blockIdx.z ? label : x;
    __half* dst      = blockIdx.z ? g_lTh : g_xTh;

    const int node   = blockIdx.x * 32 + threadIdx.x;
    const int batch0 = blockIdx.y * 32;
#pragma unroll
    for (int j = 0; j < 32; j += 8)
        tile[threadIdx.x][threadIdx.y + j] =
            src[(size_t)(batch0 + threadIdx.y + j) * N_DIM + node];
    __syncthreads();

    const int lid = threadIdx.y * 32 + threadIdx.x;   // 0..255
#pragma unroll
    for (int i = lid; i < 512; i += 256) {
        int nr = i >> 4, cp = i & 15;
        __half2 h = __floats2half2_rn(tile[nr][2 * cp], tile[nr][2 * cp + 1]);
        *(__half2*)&dst[(size_t)(blockIdx.x * 32 + nr) * B_DIM
                        + blockIdx.y * 32 + 2 * cp] = h;
    }
}

// ---------------------------------------------------------------------------
// Kernel 2: A[q*8192 + r] = relu( sum_j w0[j]*xT[adj[q][j]][r]
//                                + sum_j w1[j]*lT[adj[q][j]][r] + cb ), fp16.
// ---------------------------------------------------------------------------
__global__ __launch_bounds__(256) void build_A_kernel(
    const int* __restrict__ adj,
    const float* __restrict__ conv_w,
    const float* __restrict__ conv_b)
{
    const int q = blockIdx.y;
    const int r = blockIdx.x * 1024 + threadIdx.x * 4;

    float w[8];
#pragma unroll
    for (int j = 0; j < 8; j++) w[j] = __ldg(&conv_w[j]);
    const float cb = __ldg(&conv_b[0]);

    const int c0 = __ldg(&adj[q * 4 + 0]);
    const int c1 = __ldg(&adj[q * 4 + 1]);
    const int c2 = __ldg(&adj[q * 4 + 2]);
    const int c3 = __ldg(&adj[q * 4 + 3]);

    float4 acc = make_float4(cb, cb, cb, cb);
#define ACC4(buf, col, wj)                                                    \
    {                                                                         \
        uint2 raw = *(const uint2*)&buf[(size_t)(col) * B_DIM + r];           \
        float2 v0 = __half22float2(*(const __half2*)&raw.x);                  \
        float2 v1 = __half22float2(*(const __half2*)&raw.y);                  \
        acc.x = fmaf((wj), v0.x, acc.x);                                      \
        acc.y = fmaf((wj), v0.y, acc.y);                                      \
        acc.z = fmaf((wj), v1.x, acc.z);                                      \
        acc.w = fmaf((wj), v1.y, acc.w);                                      \
    }
    ACC4(g_xTh, c0, w[0]); ACC4(g_xTh, c1, w[1]);
    ACC4(g_xTh, c2, w[2]); ACC4(g_xTh, c3, w[3]);
    ACC4(g_lTh, c0, w[4]); ACC4(g_lTh, c1, w[5]);
    ACC4(g_lTh, c2, w[6]); ACC4(g_lTh, c3, w[7]);
#undef ACC4

    __half2 h01 = __floats2half2_rn(fmaxf(acc.x, 0.f), fmaxf(acc.y, 0.f));
    __half2 h23 = __floats2half2_rn(fmaxf(acc.z, 0.f), fmaxf(acc.w, 0.f));

    __half2* ph = (__half2*)&g_Af[(size_t)q * B_DIM + r];
    ph[0] = h01; ph[1] = h23;
}

// ---------------------------------------------------------------------------
// Kernel 3: convert lin_w to fp16
// ---------------------------------------------------------------------------
__global__ __launch_bounds__(256) void conv_W_kernel(const float* __restrict__ W)
{
    const size_t i = ((size_t)blockIdx.x * 256 + threadIdx.x) * 4;
    float4 v = __ldg((const float4*)(W + i));
    __half2* ph = (__half2*)&g_Wf[i];
    ph[0] = __floats2half2_rn(v.x, v.y);
    ph[1] = __floats2half2_rn(v.z, v.w);
}

// ---------------------------------------------------------------------------
// Kernel 4: mma.sync fp16 GEMM  C = Af @ Wf^T + b
// M=8192, N=2048, K=2048. CTA 128x128, BK=32 (SW64 rows), 4-stage cp.async,
// 8 warps (2m x 4n), warp tile 64x32, 2 CTAs/SM, 1 syncthreads/iter,
// hoisted swizzled LDSM offsets.
// ---------------------------------------------------------------------------
static constexpr int BM = 128, BN = 128, BK = 32;
static constexpr int NSTEP = N_DIM / BK;                 // 64
static constexpr int NSTAGE = 4;
static constexpr uint32_t TILE_B  = BM * BK * 2;         // 8192 per matrix
static constexpr uint32_t STAGE_B = 2 * TILE_B;          // 16384 (Af, Wf)
static constexpr uint32_t GEMM_SMEM = NSTAGE * STAGE_B;  // 65536

__device__ __forceinline__ void load_stage(uint32_t sbase, int stage,
                                           int m0, int n0, int k0, int tid)
{
    const uint32_t st = sbase + (uint32_t)stage * STAGE_B;
#pragma unroll
    for (int i = 0; i < 2; i++) {
        int idx = tid + i * 256;          // 0..511
        int row = idx >> 2;               // 0..127
        int ch  = idx & 3;                // 16B chunk within 64B row
        uint32_t so = SW64((uint32_t)(row * 64 + ch * 16));
        cp16(st + so,          g_Af + (size_t)(m0 + row) * N_DIM + k0 + ch * 8);
        cp16(st + TILE_B + so, g_Wf + (size_t)(n0 + row) * N_DIM + k0 + ch * 8);
    }
}

__global__ __launch_bounds__(256, 2) void gemm_mma_kernel(
    const float* __restrict__ bias, float* __restrict__ C)
{
    extern __shared__ char smem[];
    const uint32_t sbase = smem_u32(smem);
    const int tid  = threadIdx.x;
    const int wid  = tid >> 5;
    const int lane = tid & 31;
    const int n0 = blockIdx.x * BN;
    const int m0 = blockIdx.y * BM;

    const int warp_row = (wid >> 2) * 64;   // 0 or 64
    const int warp_col = (wid & 3) * 32;    // 0,32,64,96

    // hoisted swizzled LDSM offsets (relative to stage base)
    uint32_t offA[2][4], offB[2][2];
#pragma unroll
    for (int ks = 0; ks < 2; ks++) {
        const int ch = ks * 2 + (lane >> 4);
#pragma unroll
        for (int mf = 0; mf < 4; mf++) {
            int row = warp_row + mf * 16 + (lane & 15);
            offA[ks][mf] = SW64((uint32_t)(row * 64 + ch * 16));
        }
#pragma unroll
        for (int g = 0; g < 2; g++) {
            int n = warp_col + g * 16 + (lane & 15);
            offB[ks][g] = TILE_B + SW64((uint32_t)(n * 64 + ch * 16));
        }
    }

    float acc[4][4][4] = {};                // [m frag][n frag][reg]

    load_stage(sbase, 0, m0, n0, 0,      tid); CP_COMMIT();
    load_stage(sbase, 1, m0, n0, BK,     tid); CP_COMMIT();
    load_stage(sbase, 2, m0, n0, 2 * BK, tid); CP_COMMIT();

    for (int it = 0; it < NSTEP; ++it) {
        if (it + 2 < NSTEP)      { CP_WAIT(2); }
        else if (it + 1 < NSTEP) { CP_WAIT(1); }
        else                     { CP_WAIT(0); }
        __syncthreads();

        if (it + 3 < NSTEP) {
            load_stage(sbase, (it + 3) % NSTAGE, m0, n0, (it + 3) * BK, tid);
            CP_COMMIT();
        }

        const uint32_t st = sbase + (uint32_t)(it % NSTAGE) * STAGE_B;
#pragma unroll
        for (int ks = 0; ks < 2; ks++) {
            uint32_t a[4][4], bh[4][2];
#pragma unroll
            for (int mf = 0; mf < 4; mf++)
                ldsm_x4(a[mf], st + offA[ks][mf]);
#pragma unroll
            for (int g = 0; g < 2; g++) {
                uint32_t t[4];
                ldsm_x4(t, st + offB[ks][g]);
                bh[g * 2 + 0][0] = t[0]; bh[g * 2 + 0][1] = t[2];
                bh[g * 2 + 1][0] = t[1]; bh[g * 2 + 1][1] = t[3];
            }
#pragma unroll
            for (int mf = 0; mf < 4; mf++)
#pragma unroll
                for (int nf = 0; nf < 4; nf++)
                    mma_fp16(acc[mf][nf], a[mf], bh[nf]);
        }
        // NOTE: no trailing __syncthreads needed — 4 slots in flight are
        // pairwise distinct; top-of-loop barrier orders slot reuse.
    }

    // ----- epilogue: add bias, write C -----
    const int r_base = m0 + warp_row + (lane >> 2);
    const int c_base = n0 + warp_col + (lane & 3) * 2;
#pragma unroll
    for (int mf = 0; mf < 4; mf++)
#pragma unroll
        for (int nf = 0; nf < 4; nf++) {
            int r = r_base + mf * 16;
            int c = c_base + nf * 8;
            float b0 = __ldg(&bias[c]), b1 = __ldg(&bias[c + 1]);
            float2 v0 = make_float2(acc[mf][nf][0] + b0, acc[mf][nf][1] + b1);
            float2 v1 = make_float2(acc[mf][nf][2] + b0, acc[mf][nf][3] + b1);
            *(float2*)&C[(size_t)r * N_DIM + c]       = v0;
            *(float2*)&C[(size_t)(r + 8) * N_DIM + c] = v1;
        }
}

// ---------------------------------------------------------------------------
extern "C" void kernel_launch(void* const* d_in, const int* in_sizes, int n_in,
                              void* d_out, int out_size)
{
    const float* x      = (const float*)d_in[0];
    const float* label  = (const float*)d_in[1];
    const int*   adj    = (const int*)  d_in[2];
    const float* conv_w = (const float*)d_in[3];
    const float* conv_b = (const float*)d_in[4];
    const float* lin_w  = (const float*)d_in[5];
    const float* lin_b  = (const float*)d_in[6];
    float* out = (float*)d_out;

    {   // 1) transpose to fp16
        dim3 grid(N_DIM / 32, B_DIM / 32, 2);
        dim3 block(32, 8, 1);
        transpose_kernel<<<grid, block>>>(x, label);
    }
    {   // 2) build A (fp16)
        dim3 grid(B_DIM / (256 * 4), N_DIM, 1);
        build_A_kernel<<<grid, 256>>>(adj, conv_w, conv_b);
    }
    {   // 3) convert W to fp16
        conv_W_kernel<<<(N_DIM * N_DIM / 4) / 256, 256>>>(lin_w);
    }
    {   // 4) tensor-core GEMM via mma.sync (plain fp16, 2 CTAs/SM)
        cudaFuncSetAttribute(gemm_mma_kernel,
                             cudaFuncAttributeMaxDynamicSharedMemorySize,
                             GEMM_SMEM);
        dim3 grid(N_DIM / BN, B_DIM / BM, 1);
        gemm_mma_kernel<<<grid, 256, GEMM_SMEM>>>(lin_b, out);
    }
}